// round 6
// baseline (speedup 1.0000x reference)
#include <cuda_runtime.h>
#include <cuda_bf16.h>
#include <cstdint>

#define NV 8192
#define NC 128

// -------------------- device scratch (no allocs allowed) --------------------
__device__ __nv_bfloat16 g_Ehi[(size_t)NV * NV];
__device__ __nv_bfloat16 g_Elo[(size_t)NV * NV];
__device__ __nv_bfloat16 g_xh[NV * NC];
__device__ __nv_bfloat16 g_xl[NV * NC];
__device__ __nv_bfloat16 g_yh[NV * NC];
__device__ __nv_bfloat16 g_yl[NV * NC];
__device__ float g_part[2][NV * NC];     // split-K partials
__device__ float g_E0[64 * NC];
__device__ float g_E1[128 * NC];

// -------------------- small kernels ------------------------------------------
__global__ void coef_kernel(const float* __restrict__ ev0,
                            const float* __restrict__ ev1,
                            const float* __restrict__ dt) {
    int c = threadIdx.x;
    int b = blockIdx.x;
    if (b < 64) g_E0[b * NC + c] = __expf(-ev0[b] * dt[c]);
    else        g_E1[(b - 64) * NC + c] = __expf(-ev1[b - 64] * dt[NC + c]);
}

__device__ __forceinline__ uint32_t pack_bf2(__nv_bfloat16 a, __nv_bfloat16 b) {
    __nv_bfloat162 p{a, b};
    return *(uint32_t*)&p;
}

__global__ void __launch_bounds__(256) convE_kernel(const float4* __restrict__ E4,
                                                    uint2* __restrict__ Eh,
                                                    uint2* __restrict__ El) {
    const size_t N4 = (size_t)NV * NV / 4;
    for (size_t idx = (size_t)blockIdx.x * 256 + threadIdx.x; idx < N4;
         idx += (size_t)gridDim.x * 256) {
        float4 v = E4[idx];
        __nv_bfloat16 h0 = __float2bfloat16(v.x), h1 = __float2bfloat16(v.y);
        __nv_bfloat16 h2 = __float2bfloat16(v.z), h3 = __float2bfloat16(v.w);
        __nv_bfloat16 l0 = __float2bfloat16(v.x - __bfloat162float(h0));
        __nv_bfloat16 l1 = __float2bfloat16(v.y - __bfloat162float(h1));
        __nv_bfloat16 l2 = __float2bfloat16(v.z - __bfloat162float(h2));
        __nv_bfloat16 l3 = __float2bfloat16(v.w - __bfloat162float(h3));
        Eh[idx] = make_uint2(pack_bf2(h0, h1), pack_bf2(h2, h3));
        El[idx] = make_uint2(pack_bf2(l0, l1), pack_bf2(l2, l3));
    }
}

__global__ void __launch_bounds__(256) prepx_kernel(const float4* __restrict__ x4,
                                                    const float* __restrict__ mass,
                                                    uint2* __restrict__ xh,
                                                    uint2* __restrict__ xl) {
    int idx = blockIdx.x * 256 + threadIdx.x;
    float m = mass[(idx * 4) >> 7];
    float4 v = x4[idx];
    float a = v.x * m, b = v.y * m, c = v.z * m, d = v.w * m;
    __nv_bfloat16 h0 = __float2bfloat16(a), h1 = __float2bfloat16(b);
    __nv_bfloat16 h2 = __float2bfloat16(c), h3 = __float2bfloat16(d);
    __nv_bfloat16 l0 = __float2bfloat16(a - __bfloat162float(h0));
    __nv_bfloat16 l1 = __float2bfloat16(b - __bfloat162float(h1));
    __nv_bfloat16 l2 = __float2bfloat16(c - __bfloat162float(h2));
    __nv_bfloat16 l3 = __float2bfloat16(d - __bfloat162float(h3));
    xh[idx] = make_uint2(pack_bf2(h0, h1), pack_bf2(h2, h3));
    xl[idx] = make_uint2(pack_bf2(l0, l1), pack_bf2(l2, l3));
}

// reduce split-K partials; apply coef; emit bf16 hi/lo for GEMM2
__global__ void __launch_bounds__(256) reduce1_kernel(const float4* __restrict__ P0,
                                                      const float4* __restrict__ P1,
                                                      uint2* __restrict__ yh,
                                                      uint2* __restrict__ yl,
                                                      const float4* __restrict__ E0,
                                                      const float4* __restrict__ E1) {
    int idx = blockIdx.x * 256 + threadIdx.x;       // over NV*NC/4
    int gm = (idx * 4) >> 7;
    int gn4 = (idx & 31);                            // float4 index within row
    float4 a = P0[idx], b = P1[idx];
    float4 c0 = E0[(gm >> 7) * 32 + gn4];
    float4 c1 = E1[(gm & 127) * 32 + gn4];
    float v0 = (a.x + b.x) * c0.x * c1.x;
    float v1 = (a.y + b.y) * c0.y * c1.y;
    float v2 = (a.z + b.z) * c0.z * c1.z;
    float v3 = (a.w + b.w) * c0.w * c1.w;
    __nv_bfloat16 h0 = __float2bfloat16(v0), h1 = __float2bfloat16(v1);
    __nv_bfloat16 h2 = __float2bfloat16(v2), h3 = __float2bfloat16(v3);
    __nv_bfloat16 l0 = __float2bfloat16(v0 - __bfloat162float(h0));
    __nv_bfloat16 l1 = __float2bfloat16(v1 - __bfloat162float(h1));
    __nv_bfloat16 l2 = __float2bfloat16(v2 - __bfloat162float(h2));
    __nv_bfloat16 l3 = __float2bfloat16(v3 - __bfloat162float(h3));
    yh[idx] = make_uint2(pack_bf2(h0, h1), pack_bf2(h2, h3));
    yl[idx] = make_uint2(pack_bf2(l0, l1), pack_bf2(l2, l3));
}

__global__ void __launch_bounds__(256) reduce2_kernel(const float4* __restrict__ P0,
                                                      const float4* __restrict__ P1,
                                                      float4* __restrict__ out) {
    int idx = blockIdx.x * 256 + threadIdx.x;
    float4 a = P0[idx], b = P1[idx];
    out[idx] = make_float4(a.x + b.x, a.y + b.y, a.z + b.z, a.w + b.w);
}

// -------------------- mma.sync helpers ----------------------------------------
__device__ __forceinline__ void ldsm4(uint32_t* r, uint32_t addr) {
    asm volatile("ldmatrix.sync.aligned.m8n8.x4.shared.b16 {%0,%1,%2,%3}, [%4];"
                 : "=r"(r[0]), "=r"(r[1]), "=r"(r[2]), "=r"(r[3]) : "r"(addr));
}
__device__ __forceinline__ void ldsm4t(uint32_t* r, uint32_t addr) {
    asm volatile("ldmatrix.sync.aligned.m8n8.x4.trans.shared.b16 {%0,%1,%2,%3}, [%4];"
                 : "=r"(r[0]), "=r"(r[1]), "=r"(r[2]), "=r"(r[3]) : "r"(addr));
}
__device__ __forceinline__ void mma16816(float* d, const uint32_t* a, const uint32_t* b) {
    asm volatile("mma.sync.aligned.m16n8k16.row.col.f32.bf16.bf16.f32 "
                 "{%0,%1,%2,%3}, {%4,%5,%6,%7}, {%8,%9}, {%0,%1,%2,%3};"
                 : "+f"(d[0]), "+f"(d[1]), "+f"(d[2]), "+f"(d[3])
                 : "r"(a[0]), "r"(a[1]), "r"(a[2]), "r"(a[3]),
                   "r"(b[0]), "r"(b[1]));
}
#define CP16(dst, src) \
    asm volatile("cp.async.cg.shared.global [%0], [%1], 16;" :: "r"(dst), "l"(src) : "memory")

// -------------------- GEMM config ----------------------------------------------
#define BM 64
#define BN 128
#define BK 64
#define APAD 72
#define BPAD 136
#define A_HALVES (BK * APAD)
#define B_HALVES (BK * BPAD)
#define A_BYTES  (A_HALVES * 2)      // 9216
#define B_BYTES  (B_HALVES * 2)      // 17408
#define STAGE_BYTES (2 * A_BYTES + 2 * B_BYTES)   // 53248
#define NSTAGE 2
#define SMEM_BYTES (NSTAGE * STAGE_BYTES)         // 106496  -> 2 CTAs/SM

// Split-K GEMM partial: P[m,n] = sum_{k in half} Aop[m,k]*B[k,n]; bf16 hi/lo 3-term.
// blockIdx.x = M tile, blockIdx.y = K half.
template <int TRANS_A>
__global__ void __launch_bounds__(256, 2)
gemm_kernel(const __nv_bfloat16* __restrict__ Ahi, const __nv_bfloat16* __restrict__ Alo,
            const __nv_bfloat16* __restrict__ Bhi, const __nv_bfloat16* __restrict__ Blo,
            float* __restrict__ P)
{
    extern __shared__ __nv_bfloat16 sm[];
    const uint32_t smbase = (uint32_t)__cvta_generic_to_shared(sm);
    const int tid  = threadIdx.x;
    const int lane = tid & 31, wid = tid >> 5;
    const int wm   = wid >> 2, wn = wid & 3;       // 2 x 4 warp grid (32x32 tiles)
    const int m0   = blockIdx.x * BM;
    const int kbase = blockIdx.y * (NV / 2);
    float* Pout = P + (size_t)blockIdx.y * NV * NC;

    auto issue = [&](int kt, int s) {
        const int k0 = kbase + kt * BK;
        const uint32_t sb = smbase + s * STAGE_BYTES;
#pragma unroll
        for (int i = 0; i < 2; i++) {
            int idx = i * 256 + tid;
            int r = idx >> 3, q = idx & 7;
            size_t ga = TRANS_A ? (size_t)(k0 + r) * NV + m0 + q * 8
                                : (size_t)(m0 + r) * NV + k0 + q * 8;
            uint32_t so = sb + (uint32_t)(r * APAD + q * 8) * 2;
            CP16(so, (const void*)(Ahi + ga));
            CP16(so + A_BYTES, (const void*)(Alo + ga));
        }
#pragma unroll
        for (int i = 0; i < 4; i++) {
            int idx = i * 256 + tid;
            int r = idx >> 4, q = idx & 15;
            size_t gb = (size_t)(k0 + r) * NC + q * 8;
            uint32_t so = sb + 2 * A_BYTES + (uint32_t)(r * BPAD + q * 8) * 2;
            CP16(so, (const void*)(Bhi + gb));
            CP16(so + B_BYTES, (const void*)(Blo + gb));
        }
        asm volatile("cp.async.commit_group;" ::: "memory");
    };

    float acc[2][4][4];
#pragma unroll
    for (int a = 0; a < 2; a++)
#pragma unroll
        for (int b = 0; b < 4; b++)
#pragma unroll
            for (int q = 0; q < 4; q++) acc[a][b][q] = 0.0f;

    auto compute = [&](int s) {
        const uint32_t Ahb = smbase + s * STAGE_BYTES;
        const uint32_t Bhb = Ahb + 2 * A_BYTES;
#pragma unroll
        for (int ks = 0; ks < 4; ks++) {
            uint32_t ah[2][4], al[2][4], bh[2][4], bl[2][4];
#pragma unroll
            for (int mi = 0; mi < 2; mi++) {
                uint32_t addr;
                if (TRANS_A) {
                    int krow = ks * 16 + (lane & 7) + ((lane >> 4) << 3);
                    int mcol = wm * 32 + mi * 16 + (lane & 8);
                    addr = Ahb + (uint32_t)(krow * APAD + mcol) * 2;
                    ldsm4t(ah[mi], addr);
                    ldsm4t(al[mi], addr + A_BYTES);
                } else {
                    int mrow = wm * 32 + mi * 16 + (lane & 15);
                    int kcol = ks * 16 + ((lane >> 4) << 3);
                    addr = Ahb + (uint32_t)(mrow * APAD + kcol) * 2;
                    ldsm4(ah[mi], addr);
                    ldsm4(al[mi], addr + A_BYTES);
                }
            }
#pragma unroll
            for (int nj2 = 0; nj2 < 2; nj2++) {
                int krow = ks * 16 + (lane & 15);
                int ncol = wn * 32 + nj2 * 16 + ((lane >> 4) << 3);
                uint32_t addr = Bhb + (uint32_t)(krow * BPAD + ncol) * 2;
                ldsm4t(bh[nj2], addr);
                ldsm4t(bl[nj2], addr + B_BYTES);
            }
            // term-major: 8 independent accumulators per sweep
#pragma unroll
            for (int mi = 0; mi < 2; mi++)
#pragma unroll
                for (int nj = 0; nj < 4; nj++)
                    mma16816(acc[mi][nj], ah[mi], &bh[nj >> 1][(nj & 1) * 2]);
#pragma unroll
            for (int mi = 0; mi < 2; mi++)
#pragma unroll
                for (int nj = 0; nj < 4; nj++)
                    mma16816(acc[mi][nj], ah[mi], &bl[nj >> 1][(nj & 1) * 2]);
#pragma unroll
            for (int mi = 0; mi < 2; mi++)
#pragma unroll
                for (int nj = 0; nj < 4; nj++)
                    mma16816(acc[mi][nj], al[mi], &bh[nj >> 1][(nj & 1) * 2]);
        }
    };

    const int NIT = (NV / 2) / BK;   // 64
    issue(0, 0);
#pragma unroll 1
    for (int kt = 0; kt < NIT; kt++) {
        asm volatile("cp.async.wait_group 0;" ::: "memory");
        __syncthreads();
        if (kt + 1 < NIT) issue(kt + 1, (kt + 1) & 1);   // overlaps with compute
        compute(kt & 1);
        __syncthreads();
    }

    // ---- epilogue: fp32 partials ----
#pragma unroll
    for (int mi = 0; mi < 2; mi++) {
#pragma unroll
        for (int q = 0; q < 2; q++) {
            int gm = m0 + wm * 32 + mi * 16 + (lane >> 2) + q * 8;
#pragma unroll
            for (int nj = 0; nj < 4; nj++) {
                int gn = wn * 32 + nj * 8 + (lane & 3) * 2;
                *(float2*)&Pout[(size_t)gm * NC + gn] =
                    make_float2(acc[mi][nj][q * 2 + 0], acc[mi][nj][q * 2 + 1]);
            }
        }
    }
}

// -------------------- launch -----------------------------------------------------
extern "C" void kernel_launch(void* const* d_in, const int* in_sizes, int n_in,
                              void* d_out, int out_size) {
    const float* x      = (const float*)d_in[0];
    const float* mass   = (const float*)d_in[3];
    const float* evals0 = (const float*)d_in[4];
    const float* evals1 = (const float*)d_in[5];
    const float* evecs  = (const float*)d_in[6];
    const float* dt     = (const float*)d_in[7];
    float* out          = (float*)d_out;

    __nv_bfloat16 *Eh, *El, *xh, *xl, *yh, *yl;
    float *P, *E0, *E1;
    cudaGetSymbolAddress((void**)&Eh, g_Ehi);
    cudaGetSymbolAddress((void**)&El, g_Elo);
    cudaGetSymbolAddress((void**)&xh, g_xh);
    cudaGetSymbolAddress((void**)&xl, g_xl);
    cudaGetSymbolAddress((void**)&yh, g_yh);
    cudaGetSymbolAddress((void**)&yl, g_yl);
    cudaGetSymbolAddress((void**)&P,  g_part);
    cudaGetSymbolAddress((void**)&E0, g_E0);
    cudaGetSymbolAddress((void**)&E1, g_E1);

    cudaFuncSetAttribute(gemm_kernel<1>, cudaFuncAttributeMaxDynamicSharedMemorySize, SMEM_BYTES);
    cudaFuncSetAttribute(gemm_kernel<0>, cudaFuncAttributeMaxDynamicSharedMemorySize, SMEM_BYTES);

    coef_kernel<<<192, 128>>>(evals0, evals1, dt);
    convE_kernel<<<2368, 256>>>((const float4*)evecs, (uint2*)Eh, (uint2*)El);
    prepx_kernel<<<NV * NC / 4 / 256, 256>>>((const float4*)x, mass, (uint2*)xh, (uint2*)xl);

    const int NQ = NV * NC / 4 / 256;   // reduce grid
    // GEMM1 partials: P = E^T @ xw (split-K over 2 halves)
    gemm_kernel<1><<<dim3(NV / BM, 2), 256, SMEM_BYTES>>>(Eh, El, xh, xl, P);
    // y = coef .* (P0 + P1), split to bf16 hi/lo
    reduce1_kernel<<<NQ, 256>>>((const float4*)P, (const float4*)(P + NV * NC),
                                (uint2*)yh, (uint2*)yl,
                                (const float4*)E0, (const float4*)E1);
    // GEMM2 partials: P = E @ y
    gemm_kernel<0><<<dim3(NV / BM, 2), 256, SMEM_BYTES>>>(Eh, El, yh, yl, P);
    // out = P0 + P1
    reduce2_kernel<<<NQ, 256>>>((const float4*)P, (const float4*)(P + NV * NC), (float4*)out);
}

// round 7
// speedup vs baseline: 1.0049x; 1.0049x over previous
#include <cuda_runtime.h>
#include <cuda_bf16.h>
#include <cstdint>

#define NV 8192
#define NC 128

// -------------------- device scratch (no allocs allowed) --------------------
__device__ __nv_bfloat16 g_Ehi[(size_t)NV * NV];
__device__ __nv_bfloat16 g_Elo[(size_t)NV * NV];
__device__ __nv_bfloat16 g_xh[NV * NC];
__device__ __nv_bfloat16 g_xl[NV * NC];
__device__ __nv_bfloat16 g_yh[NV * NC];
__device__ __nv_bfloat16 g_yl[NV * NC];
__device__ float g_part[2][NV * NC];
__device__ float g_E0[64 * NC];
__device__ float g_E1[128 * NC];

// -------------------- small kernels ------------------------------------------
__global__ void coef_kernel(const float* __restrict__ ev0,
                            const float* __restrict__ ev1,
                            const float* __restrict__ dt) {
    int c = threadIdx.x;
    int b = blockIdx.x;
    if (b < 64) g_E0[b * NC + c] = __expf(-ev0[b] * dt[c]);
    else        g_E1[(b - 64) * NC + c] = __expf(-ev1[b - 64] * dt[NC + c]);
}

__device__ __forceinline__ uint32_t pack_bf2(__nv_bfloat16 a, __nv_bfloat16 b) {
    __nv_bfloat162 p{a, b};
    return *(uint32_t*)&p;
}

__global__ void __launch_bounds__(256) convE_kernel(const float4* __restrict__ E4,
                                                    uint2* __restrict__ Eh,
                                                    uint2* __restrict__ El) {
    const size_t N4 = (size_t)NV * NV / 4;
    for (size_t idx = (size_t)blockIdx.x * 256 + threadIdx.x; idx < N4;
         idx += (size_t)gridDim.x * 256) {
        float4 v = E4[idx];
        __nv_bfloat16 h0 = __float2bfloat16(v.x), h1 = __float2bfloat16(v.y);
        __nv_bfloat16 h2 = __float2bfloat16(v.z), h3 = __float2bfloat16(v.w);
        __nv_bfloat16 l0 = __float2bfloat16(v.x - __bfloat162float(h0));
        __nv_bfloat16 l1 = __float2bfloat16(v.y - __bfloat162float(h1));
        __nv_bfloat16 l2 = __float2bfloat16(v.z - __bfloat162float(h2));
        __nv_bfloat16 l3 = __float2bfloat16(v.w - __bfloat162float(h3));
        Eh[idx] = make_uint2(pack_bf2(h0, h1), pack_bf2(h2, h3));
        El[idx] = make_uint2(pack_bf2(l0, l1), pack_bf2(l2, l3));
    }
}

__global__ void __launch_bounds__(256) prepx_kernel(const float4* __restrict__ x4,
                                                    const float* __restrict__ mass,
                                                    uint2* __restrict__ xh,
                                                    uint2* __restrict__ xl) {
    int idx = blockIdx.x * 256 + threadIdx.x;
    float m = mass[(idx * 4) >> 7];
    float4 v = x4[idx];
    float a = v.x * m, b = v.y * m, c = v.z * m, d = v.w * m;
    __nv_bfloat16 h0 = __float2bfloat16(a), h1 = __float2bfloat16(b);
    __nv_bfloat16 h2 = __float2bfloat16(c), h3 = __float2bfloat16(d);
    __nv_bfloat16 l0 = __float2bfloat16(a - __bfloat162float(h0));
    __nv_bfloat16 l1 = __float2bfloat16(b - __bfloat162float(h1));
    __nv_bfloat16 l2 = __float2bfloat16(c - __bfloat162float(h2));
    __nv_bfloat16 l3 = __float2bfloat16(d - __bfloat162float(h3));
    xh[idx] = make_uint2(pack_bf2(h0, h1), pack_bf2(h2, h3));
    xl[idx] = make_uint2(pack_bf2(l0, l1), pack_bf2(l2, l3));
}

__global__ void __launch_bounds__(256) reduce1_kernel(const float4* __restrict__ P0,
                                                      const float4* __restrict__ P1,
                                                      uint2* __restrict__ yh,
                                                      uint2* __restrict__ yl,
                                                      const float4* __restrict__ E0,
                                                      const float4* __restrict__ E1) {
    int idx = blockIdx.x * 256 + threadIdx.x;
    int gm = (idx * 4) >> 7;
    int gn4 = (idx & 31);
    float4 a = P0[idx], b = P1[idx];
    float4 c0 = E0[(gm >> 7) * 32 + gn4];
    float4 c1 = E1[(gm & 127) * 32 + gn4];
    float v0 = (a.x + b.x) * c0.x * c1.x;
    float v1 = (a.y + b.y) * c0.y * c1.y;
    float v2 = (a.z + b.z) * c0.z * c1.z;
    float v3 = (a.w + b.w) * c0.w * c1.w;
    __nv_bfloat16 h0 = __float2bfloat16(v0), h1 = __float2bfloat16(v1);
    __nv_bfloat16 h2 = __float2bfloat16(v2), h3 = __float2bfloat16(v3);
    __nv_bfloat16 l0 = __float2bfloat16(v0 - __bfloat162float(h0));
    __nv_bfloat16 l1 = __float2bfloat16(v1 - __bfloat162float(h1));
    __nv_bfloat16 l2 = __float2bfloat16(v2 - __bfloat162float(h2));
    __nv_bfloat16 l3 = __float2bfloat16(v3 - __bfloat162float(h3));
    yh[idx] = make_uint2(pack_bf2(h0, h1), pack_bf2(h2, h3));
    yl[idx] = make_uint2(pack_bf2(l0, l1), pack_bf2(l2, l3));
}

__global__ void __launch_bounds__(256) reduce2_kernel(const float4* __restrict__ P0,
                                                      const float4* __restrict__ P1,
                                                      float4* __restrict__ out) {
    int idx = blockIdx.x * 256 + threadIdx.x;
    float4 a = P0[idx], b = P1[idx];
    out[idx] = make_float4(a.x + b.x, a.y + b.y, a.z + b.z, a.w + b.w);
}

// -------------------- mma.sync helpers ----------------------------------------
__device__ __forceinline__ void ldsm4(uint32_t* r, uint32_t addr) {
    asm volatile("ldmatrix.sync.aligned.m8n8.x4.shared.b16 {%0,%1,%2,%3}, [%4];"
                 : "=r"(r[0]), "=r"(r[1]), "=r"(r[2]), "=r"(r[3]) : "r"(addr));
}
__device__ __forceinline__ void ldsm4t(uint32_t* r, uint32_t addr) {
    asm volatile("ldmatrix.sync.aligned.m8n8.x4.trans.shared.b16 {%0,%1,%2,%3}, [%4];"
                 : "=r"(r[0]), "=r"(r[1]), "=r"(r[2]), "=r"(r[3]) : "r"(addr));
}
__device__ __forceinline__ void mma16816(float* d, const uint32_t* a, const uint32_t* b) {
    asm volatile("mma.sync.aligned.m16n8k16.row.col.f32.bf16.bf16.f32 "
                 "{%0,%1,%2,%3}, {%4,%5,%6,%7}, {%8,%9}, {%0,%1,%2,%3};"
                 : "+f"(d[0]), "+f"(d[1]), "+f"(d[2]), "+f"(d[3])
                 : "r"(a[0]), "r"(a[1]), "r"(a[2]), "r"(a[3]),
                   "r"(b[0]), "r"(b[1]));
}
#define CP16(dst, src) \
    asm volatile("cp.async.cg.shared.global [%0], [%1], 16;" :: "r"(dst), "l"(src) : "memory")

// -------------------- GEMM config ----------------------------------------------
// BM=128, BN=128, BK=64. Warp grid 4(M) x 2(N); warp tile 32x64.
// TRANS_A: A tile stored [64 k-rows][128 m-cols]; else [128 m-rows][64 k-cols].
#define BM 128
#define BK 64

template <int TRANS_A>
struct Cfg {
    static constexpr int A_ROWS = TRANS_A ? 64 : 128;
    static constexpr int A_PAD  = TRANS_A ? 136 : 72;     // cols + 8 halves
    static constexpr int A_HALVES = A_ROWS * A_PAD;
    static constexpr int B_PAD  = 136;
    static constexpr int B_HALVES = 64 * B_PAD;
    static constexpr int A_BYTES = A_HALVES * 2;
    static constexpr int B_BYTES = B_HALVES * 2;
    static constexpr int STAGE = 2 * A_BYTES + 2 * B_BYTES;
    static constexpr int SMEM = 2 * STAGE;
};

// Split-K GEMM partial: blockIdx.x = M tile (64), blockIdx.y = K half (2).
template <int TRANS_A>
__global__ void __launch_bounds__(256, 1)
gemm_kernel(const __nv_bfloat16* __restrict__ Ahi, const __nv_bfloat16* __restrict__ Alo,
            const __nv_bfloat16* __restrict__ Bhi, const __nv_bfloat16* __restrict__ Blo,
            float* __restrict__ P)
{
    using C = Cfg<TRANS_A>;
    extern __shared__ __nv_bfloat16 sm[];
    const uint32_t smbase = (uint32_t)__cvta_generic_to_shared(sm);
    const int tid  = threadIdx.x;
    const int lane = tid & 31, wid = tid >> 5;
    const int wm   = wid >> 1, wn = wid & 1;      // 4 x 2 warps, tile 32x64
    const int m0   = blockIdx.x * BM;
    const int kbase = blockIdx.y * (NV / 2);
    float* Pout = P + (size_t)blockIdx.y * NV * NC;

    auto issue = [&](int kt, int s) {
        const int k0 = kbase + kt * BK;
        const uint32_t sb = smbase + s * C::STAGE;
#pragma unroll
        for (int i = 0; i < 4; i++) {             // A: 1024 16B chunks per buf
            int idx = i * 256 + tid;
            int r, q;
            size_t ga;
            uint32_t so;
            if (TRANS_A) {
                r = idx >> 4; q = idx & 15;       // 64 rows x 16 chunks
                ga = (size_t)(k0 + r) * NV + m0 + q * 8;
                so = (uint32_t)(r * C::A_PAD + q * 8) * 2;
            } else {
                r = idx >> 3; q = idx & 7;        // 128 rows x 8 chunks
                ga = (size_t)(m0 + r) * NV + k0 + q * 8;
                so = (uint32_t)(r * C::A_PAD + q * 8) * 2;
            }
            CP16(sb + so, (const void*)(Ahi + ga));
            CP16(sb + so + C::A_BYTES, (const void*)(Alo + ga));
        }
#pragma unroll
        for (int i = 0; i < 4; i++) {             // B: 1024 chunks per buf
            int idx = i * 256 + tid;
            int r = idx >> 4, q = idx & 15;
            size_t gb = (size_t)(k0 + r) * NC + q * 8;
            uint32_t so = 2 * C::A_BYTES + (uint32_t)(r * C::B_PAD + q * 8) * 2;
            CP16(sb + so, (const void*)(Bhi + gb));
            CP16(sb + so + C::B_BYTES, (const void*)(Blo + gb));
        }
        asm volatile("cp.async.commit_group;" ::: "memory");
    };

    float acc[2][8][4];
#pragma unroll
    for (int a = 0; a < 2; a++)
#pragma unroll
        for (int b = 0; b < 8; b++)
#pragma unroll
            for (int q = 0; q < 4; q++) acc[a][b][q] = 0.0f;

    auto compute = [&](int s) {
        const uint32_t Ahb = smbase + s * C::STAGE;
        const uint32_t Bhb = Ahb + 2 * C::A_BYTES;
#pragma unroll
        for (int ks = 0; ks < 4; ks++) {
            uint32_t ah[2][4], al[2][4], bh[4][4], bl[4][4];
#pragma unroll
            for (int mi = 0; mi < 2; mi++) {
                uint32_t addr;
                if (TRANS_A) {
                    int krow = ks * 16 + (lane & 7) + ((lane >> 4) << 3);
                    int mcol = wm * 32 + mi * 16 + (lane & 8);
                    addr = Ahb + (uint32_t)(krow * C::A_PAD + mcol) * 2;
                    ldsm4t(ah[mi], addr);
                    ldsm4t(al[mi], addr + C::A_BYTES);
                } else {
                    int mrow = wm * 32 + mi * 16 + (lane & 15);
                    int kcol = ks * 16 + ((lane >> 4) << 3);
                    addr = Ahb + (uint32_t)(mrow * C::A_PAD + kcol) * 2;
                    ldsm4(ah[mi], addr);
                    ldsm4(al[mi], addr + C::A_BYTES);
                }
            }
#pragma unroll
            for (int nj2 = 0; nj2 < 4; nj2++) {
                int krow = ks * 16 + (lane & 15);
                int ncol = wn * 64 + nj2 * 16 + ((lane >> 4) << 3);
                uint32_t addr = Bhb + (uint32_t)(krow * C::B_PAD + ncol) * 2;
                ldsm4t(bh[nj2], addr);
                ldsm4t(bl[nj2], addr + C::B_BYTES);
            }
            // 3 term-major sweeps of 16 independent accumulators
#pragma unroll
            for (int mi = 0; mi < 2; mi++)
#pragma unroll
                for (int nj = 0; nj < 8; nj++)
                    mma16816(acc[mi][nj], ah[mi], &bh[nj >> 1][(nj & 1) * 2]);
#pragma unroll
            for (int mi = 0; mi < 2; mi++)
#pragma unroll
                for (int nj = 0; nj < 8; nj++)
                    mma16816(acc[mi][nj], ah[mi], &bl[nj >> 1][(nj & 1) * 2]);
#pragma unroll
            for (int mi = 0; mi < 2; mi++)
#pragma unroll
                for (int nj = 0; nj < 8; nj++)
                    mma16816(acc[mi][nj], al[mi], &bh[nj >> 1][(nj & 1) * 2]);
        }
    };

    const int NIT = (NV / 2) / BK;   // 64
    issue(0, 0);
#pragma unroll 1
    for (int kt = 0; kt < NIT; kt++) {
        asm volatile("cp.async.wait_group 0;" ::: "memory");
        __syncthreads();
        if (kt + 1 < NIT) issue(kt + 1, (kt + 1) & 1);
        compute(kt & 1);
        __syncthreads();
    }

    // ---- epilogue: fp32 partials ----
#pragma unroll
    for (int mi = 0; mi < 2; mi++) {
#pragma unroll
        for (int q = 0; q < 2; q++) {
            int gm = m0 + wm * 32 + mi * 16 + (lane >> 2) + q * 8;
#pragma unroll
            for (int nj = 0; nj < 8; nj++) {
                int gn = wn * 64 + nj * 8 + (lane & 3) * 2;
                *(float2*)&Pout[(size_t)gm * NC + gn] =
                    make_float2(acc[mi][nj][q * 2 + 0], acc[mi][nj][q * 2 + 1]);
            }
        }
    }
}

// -------------------- launch -----------------------------------------------------
extern "C" void kernel_launch(void* const* d_in, const int* in_sizes, int n_in,
                              void* d_out, int out_size) {
    const float* x      = (const float*)d_in[0];
    const float* mass   = (const float*)d_in[3];
    const float* evals0 = (const float*)d_in[4];
    const float* evals1 = (const float*)d_in[5];
    const float* evecs  = (const float*)d_in[6];
    const float* dt     = (const float*)d_in[7];
    float* out          = (float*)d_out;

    __nv_bfloat16 *Eh, *El, *xh, *xl, *yh, *yl;
    float *P, *E0, *E1;
    cudaGetSymbolAddress((void**)&Eh, g_Ehi);
    cudaGetSymbolAddress((void**)&El, g_Elo);
    cudaGetSymbolAddress((void**)&xh, g_xh);
    cudaGetSymbolAddress((void**)&xl, g_xl);
    cudaGetSymbolAddress((void**)&yh, g_yh);
    cudaGetSymbolAddress((void**)&yl, g_yl);
    cudaGetSymbolAddress((void**)&P,  g_part);
    cudaGetSymbolAddress((void**)&E0, g_E0);
    cudaGetSymbolAddress((void**)&E1, g_E1);

    cudaFuncSetAttribute(gemm_kernel<1>, cudaFuncAttributeMaxDynamicSharedMemorySize, Cfg<1>::SMEM);
    cudaFuncSetAttribute(gemm_kernel<0>, cudaFuncAttributeMaxDynamicSharedMemorySize, Cfg<0>::SMEM);

    coef_kernel<<<192, 128>>>(evals0, evals1, dt);
    convE_kernel<<<2368, 256>>>((const float4*)evecs, (uint2*)Eh, (uint2*)El);
    prepx_kernel<<<NV * NC / 4 / 256, 256>>>((const float4*)x, mass, (uint2*)xh, (uint2*)xl);

    const int NQ = NV * NC / 4 / 256;
    gemm_kernel<1><<<dim3(NV / BM, 2), 256, Cfg<1>::SMEM>>>(Eh, El, xh, xl, P);
    reduce1_kernel<<<NQ, 256>>>((const float4*)P, (const float4*)(P + NV * NC),
                                (uint2*)yh, (uint2*)yl,
                                (const float4*)E0, (const float4*)E1);
    gemm_kernel<0><<<dim3(NV / BM, 2), 256, Cfg<0>::SMEM>>>(Eh, El, yh, yl, P);
    reduce2_kernel<<<NQ, 256>>>((const float4*)P, (const float4*)(P + NV * NC), (float4*)out);
}